// round 3
// baseline (speedup 1.0000x reference)
#include <cuda_runtime.h>
#include <math.h>

#define BB 2
#define CY 96
#define CS 48
#define NN 4096
#define SCALE 0.14433756729740643f  /* 48^-0.5 */

// ---------------- scratch (device globals: no runtime allocation) ----------
__device__ float g_Spe[BB*CS*NN];
__device__ float g_Ype[BB*CY*NN];
__device__ float g_Y1 [BB*NN*CS];
__device__ float g_Q  [BB*NN*CS];
__device__ float g_K  [BB*NN*CS];
__device__ float g_V  [BB*NN*CS];
__device__ float g_X  [BB*NN*CS];
__device__ float g_Y3 [BB*CY*NN];
__device__ float g_m  [BB*NN];
__device__ float g_iz [BB*NN];
__device__ float g_Lt [(size_t)BB*NN*NN];   // 128 MB: logits transposed [b][k][q]

// ---------------- positional encoding + add --------------------------------
// pe[ch, d, h, w]:  c = C/3 (exact here). blk = ch/c, t = ch%c.
//   blk 0,1 -> emb(h)[t]   (faithful torch broadcasting quirk: both x and y
//   blocks read the *h* index since x==y==16)
//   blk 2   -> emb(w)[t]
//   emb(n)[t] = t < c/2 ? sin(n*10000^{-2t/c}) : cos(n*10000^{-2(t-c/2)/c})
__device__ __forceinline__ float pe_val(int ch, int h, int w, int c) {
    int blk = ch / c, t = ch - blk * c;
    int pos = (blk < 2) ? h : w;
    int half = c >> 1;
    float val;
    if (t < half) {
        float invf = powf(10000.f, -2.f * (float)t / (float)c);
        val = sinf((float)pos * invf);
    } else {
        float invf = powf(10000.f, -2.f * (float)(t - half) / (float)c);
        val = cosf((float)pos * invf);
    }
    return val;
}

__global__ void k_addpe_s(const float* __restrict__ S) {
    int i = blockIdx.x * blockDim.x + threadIdx.x;
    if (i >= BB * CS * NN) return;
    int n = i & (NN - 1);
    int ch = (i >> 12) % CS;
    int h = (n >> 4) & 15, w = n & 15;
    g_Spe[i] = S[i] + pe_val(ch, h, w, 16);
}

__global__ void k_addpe_y(const float* __restrict__ Y) {
    int i = blockIdx.x * blockDim.x + threadIdx.x;
    if (i >= BB * CY * NN) return;
    int n = i & (NN - 1);
    int ch = (i >> 12) % CY;
    int h = (n >> 4) & 15, w = n & 15;
    g_Ype[i] = Y[i] + pe_val(ch, h, w, 32);
}

// ---------------- S1 projection fused with V = S1 @ Wv ---------------------
// block: (n-tile of 64, b). 256 threads. thread -> (n = t&63, eg = t>>6),
// each handles 12 output channels.
__global__ __launch_bounds__(256) void k_proj_sv(
    const float* __restrict__ w_s, const float* __restrict__ b_s,
    const float* __restrict__ g_s, const float* __restrict__ be_s,
    const float* __restrict__ Wv)
{
    __shared__ float in_s[CS * 64];         // [c][n]
    __shared__ float wt[CS * CS];           // wt[c*48+e] = w_s[e*48+c]
    __shared__ float wv[CS * CS];           // natural [d][e]
    __shared__ float s1[64 * 49];           // [n][d], pad 49

    int b = blockIdx.y, n0 = blockIdx.x * 64, t = threadIdx.x;
    for (int i = t; i < CS * CS; i += 256) {
        int e = i % CS, c = i / CS;
        wt[i] = w_s[e * CS + c];
        wv[i] = Wv[i];
    }
    const float* src = g_Spe + (b * CS) * NN + n0;
    for (int i = t; i < CS * 64; i += 256) {
        int c = i >> 6, n = i & 63;
        in_s[i] = src[c * NN + n];
    }
    __syncthreads();

    int n = t & 63, eg = t >> 6;
    float acc[12];
#pragma unroll
    for (int j = 0; j < 12; j++) acc[j] = 0.f;
    for (int c = 0; c < CS; c++) {
        float x = in_s[c * 64 + n];
#pragma unroll
        for (int v = 0; v < 3; v++) {
            float4 w4 = *(const float4*)&wt[c * CS + eg * 12 + v * 4];
            acc[v*4+0] += w4.x * x; acc[v*4+1] += w4.y * x;
            acc[v*4+2] += w4.z * x; acc[v*4+3] += w4.w * x;
        }
    }
    float inv = rsqrtf(1.f + 1e-5f);
#pragma unroll
    for (int j = 0; j < 12; j++) {
        int e = eg * 12 + j;
        float y = (acc[j] + b_s[e]) * (g_s[e] * inv) + be_s[e];
        s1[n * 49 + e] = fmaxf(y, 0.f);
    }
    __syncthreads();

#pragma unroll
    for (int j = 0; j < 12; j++) acc[j] = 0.f;
    for (int d = 0; d < CS; d++) {
        float x = s1[n * 49 + d];
#pragma unroll
        for (int v = 0; v < 3; v++) {
            float4 w4 = *(const float4*)&wv[d * CS + eg * 12 + v * 4];
            acc[v*4+0] += w4.x * x; acc[v*4+1] += w4.y * x;
            acc[v*4+2] += w4.z * x; acc[v*4+3] += w4.w * x;
        }
    }
    float* dst = g_V + ((b * NN + n0 + n) * CS) + eg * 12;
#pragma unroll
    for (int v = 0; v < 3; v++)
        *(float4*)&dst[v * 4] = make_float4(acc[v*4], acc[v*4+1], acc[v*4+2], acc[v*4+3]);
}

// ---------------- Y1 projection (96 -> 48) ---------------------------------
__global__ __launch_bounds__(256) void k_proj_y1(
    const float* __restrict__ w_y, const float* __restrict__ b_y,
    const float* __restrict__ g_y, const float* __restrict__ be_y)
{
    __shared__ float in_s[CY * 64];     // [c][n]
    __shared__ float wt[CY * CS];       // wt[c*48+e] = w_y[e*96+c]

    int b = blockIdx.y, n0 = blockIdx.x * 64, t = threadIdx.x;
    for (int i = t; i < CY * CS; i += 256) {
        int e = i % CS, c = i / CS;
        wt[i] = w_y[e * CY + c];
    }
    const float* src = g_Ype + (b * CY) * NN + n0;
    for (int i = t; i < CY * 64; i += 256) {
        int c = i >> 6, n = i & 63;
        in_s[i] = src[c * NN + n];
    }
    __syncthreads();

    int n = t & 63, eg = t >> 6;
    float acc[12];
#pragma unroll
    for (int j = 0; j < 12; j++) acc[j] = 0.f;
    for (int c = 0; c < CY; c++) {
        float x = in_s[c * 64 + n];
#pragma unroll
        for (int v = 0; v < 3; v++) {
            float4 w4 = *(const float4*)&wt[c * CS + eg * 12 + v * 4];
            acc[v*4+0] += w4.x * x; acc[v*4+1] += w4.y * x;
            acc[v*4+2] += w4.z * x; acc[v*4+3] += w4.w * x;
        }
    }
    float inv = rsqrtf(1.f + 1e-5f);
    float* dst = g_Y1 + ((b * NN + n0 + n) * CS) + eg * 12;
#pragma unroll
    for (int j = 0; j < 12; j++) {
        int e = eg * 12 + j;
        float y = (acc[j] + b_y[e]) * (g_y[e] * inv) + be_y[e];
        dst[j] = fmaxf(y, 0.f);
    }
}

// ---------------- Q = Y1 @ Wq, K = Y1 @ Wk ---------------------------------
__global__ __launch_bounds__(256) void k_qk(
    const float* __restrict__ Wq, const float* __restrict__ Wk)
{
    __shared__ float y1[64 * 49];       // [n][d]
    __shared__ float wq[CS * CS];       // natural [d][e]
    __shared__ float wk[CS * CS];

    int b = blockIdx.y, n0 = blockIdx.x * 64, t = threadIdx.x;
    for (int i = t; i < CS * CS; i += 256) { wq[i] = Wq[i]; wk[i] = Wk[i]; }
    const float* src = g_Y1 + (b * NN + n0) * CS;
    for (int i = t; i < 64 * CS; i += 256) {
        int n = i / CS, d = i % CS;
        y1[n * 49 + d] = src[i];
    }
    __syncthreads();

    int n = t & 63, eg = t >> 6;
    float aq[12], ak[12];
#pragma unroll
    for (int j = 0; j < 12; j++) { aq[j] = 0.f; ak[j] = 0.f; }
    for (int d = 0; d < CS; d++) {
        float x = y1[n * 49 + d];
#pragma unroll
        for (int v = 0; v < 3; v++) {
            float4 q4 = *(const float4*)&wq[d * CS + eg * 12 + v * 4];
            float4 k4 = *(const float4*)&wk[d * CS + eg * 12 + v * 4];
            aq[v*4+0] += q4.x * x; aq[v*4+1] += q4.y * x;
            aq[v*4+2] += q4.z * x; aq[v*4+3] += q4.w * x;
            ak[v*4+0] += k4.x * x; ak[v*4+1] += k4.y * x;
            ak[v*4+2] += k4.z * x; ak[v*4+3] += k4.w * x;
        }
    }
    float* dq = g_Q + ((b * NN + n0 + n) * CS) + eg * 12;
    float* dk = g_K + ((b * NN + n0 + n) * CS) + eg * 12;
#pragma unroll
    for (int v = 0; v < 3; v++) {
        *(float4*)&dq[v * 4] = make_float4(aq[v*4], aq[v*4+1], aq[v*4+2], aq[v*4+3]);
        *(float4*)&dk[v * 4] = make_float4(ak[v*4], ak[v*4+1], ak[v*4+2], ak[v*4+3]);
    }
}

// ---------------- logits: Lt[b][k][q] = SCALE * Q[q]·K[k] ------------------
// 64x64 output tile, 256 threads, 4x4 micro-tile, d=48 inner.
__global__ __launch_bounds__(256) void k_logits() {
    __shared__ float Qs[CS * 64];   // [d][q]
    __shared__ float Ks[CS * 64];   // [d][k]

    int q0 = blockIdx.x * 64, k0 = blockIdx.y * 64, b = blockIdx.z;
    int t = threadIdx.x;
    {
        int n = t & 63, v = t >> 6;
        const float* sq = g_Q + ((b * NN + q0 + n) * CS);
        const float* sk = g_K + ((b * NN + k0 + n) * CS);
#pragma unroll
        for (int r = 0; r < 3; r++) {
            int dv = v + r * 4;
            float4 x = *(const float4*)&sq[dv * 4];
            Qs[(dv*4+0)*64+n] = x.x; Qs[(dv*4+1)*64+n] = x.y;
            Qs[(dv*4+2)*64+n] = x.z; Qs[(dv*4+3)*64+n] = x.w;
            float4 y = *(const float4*)&sk[dv * 4];
            Ks[(dv*4+0)*64+n] = y.x; Ks[(dv*4+1)*64+n] = y.y;
            Ks[(dv*4+2)*64+n] = y.z; Ks[(dv*4+3)*64+n] = y.w;
        }
    }
    __syncthreads();

    int tq = t & 15, tk = t >> 4;
    float acc[4][4];
#pragma unroll
    for (int i = 0; i < 4; i++)
#pragma unroll
        for (int j = 0; j < 4; j++) acc[i][j] = 0.f;

    for (int d = 0; d < CS; d++) {
        float4 kk = *(const float4*)&Ks[d * 64 + tk * 4];
        float4 qq = *(const float4*)&Qs[d * 64 + tq * 4];
        float ka[4] = {kk.x, kk.y, kk.z, kk.w};
        float qa[4] = {qq.x, qq.y, qq.z, qq.w};
#pragma unroll
        for (int i = 0; i < 4; i++)
#pragma unroll
            for (int j = 0; j < 4; j++) acc[i][j] += ka[i] * qa[j];
    }
#pragma unroll
    for (int i = 0; i < 4; i++) {
        size_t row = (size_t)(b * NN + k0 + tk * 4 + i) * NN + q0 + tq * 4;
        *(float4*)&g_Lt[row] = make_float4(acc[i][0]*SCALE, acc[i][1]*SCALE,
                                           acc[i][2]*SCALE, acc[i][3]*SCALE);
    }
}

// ---------------- column stats: online max & sumexp over q -----------------
__global__ __launch_bounds__(256) void k_colstats() {
    int k = blockIdx.x, b = blockIdx.y;
    const float* row = g_Lt + (size_t)(b * NN + k) * NN;
    float m = -1e30f, s = 0.f;
    for (int q = threadIdx.x; q < NN; q += 256) {
        float v = row[q];
        if (v > m) { s = s * __expf(m - v) + 1.f; m = v; }
        else       { s += __expf(v - m); }
    }
#pragma unroll
    for (int o = 16; o; o >>= 1) {
        float m2 = __shfl_xor_sync(0xffffffffu, m, o);
        float s2 = __shfl_xor_sync(0xffffffffu, s, o);
        float M = fmaxf(m, m2);
        s = s * __expf(m - M) + s2 * __expf(m2 - M);
        m = M;
    }
    __shared__ float sm[8], ss[8];
    int w = threadIdx.x >> 5, l = threadIdx.x & 31;
    if (l == 0) { sm[w] = m; ss[w] = s; }
    __syncthreads();
    if (threadIdx.x == 0) {
        float M = sm[0], Ssum = ss[0];
#pragma unroll
        for (int i = 1; i < 8; i++) {
            float M2 = fmaxf(M, sm[i]);
            Ssum = Ssum * __expf(M - M2) + ss[i] * __expf(sm[i] - M2);
            M = M2;
        }
        g_m [b * NN + k] = M;
        g_iz[b * NN + k] = 1.f / Ssum;
    }
}

// ---------------- AV: x[q][d] = sum_k exp(Lt[k][q]-m[k])*izk * V[k][d] -----
__global__ __launch_bounds__(256) void k_av() {
    __shared__ float Ps[64 * 64];   // [k][q]
    __shared__ float Vs[64 * CS];   // [k][d]

    int q0 = blockIdx.x * 64, b = blockIdx.y, t = threadIdx.x;
    int tq = t & 15, td = t >> 4;
    float acc[4][3];
#pragma unroll
    for (int i = 0; i < 4; i++)
#pragma unroll
        for (int j = 0; j < 3; j++) acc[i][j] = 0.f;

    int kl = t >> 2, qb = (t & 3) * 16;
    for (int k0 = 0; k0 < NN; k0 += 64) {
        float mk = g_m [b * NN + k0 + kl];
        float zk = g_iz[b * NN + k0 + kl];
        const float* srcL = g_Lt + (size_t)(b * NN + k0 + kl) * NN + q0 + qb;
#pragma unroll
        for (int r = 0; r < 4; r++) {
            float4 x = *(const float4*)&srcL[r * 4];
            float* p = &Ps[kl * 64 + qb + r * 4];
            p[0] = __expf(x.x - mk) * zk; p[1] = __expf(x.y - mk) * zk;
            p[2] = __expf(x.z - mk) * zk; p[3] = __expf(x.w - mk) * zk;
        }
        const float* srcV = g_V + ((b * NN + k0 + kl) * CS) + (t & 3) * 12;
        float* dv = &Vs[kl * CS + (t & 3) * 12];
#pragma unroll
        for (int r = 0; r < 3; r++)
            *(float4*)&dv[r * 4] = *(const float4*)&srcV[r * 4];
        __syncthreads();

        for (int kk = 0; kk < 64; kk++) {
            float4 p = *(const float4*)&Ps[kk * 64 + tq * 4];
            float v0 = Vs[kk * CS + td * 3 + 0];
            float v1 = Vs[kk * CS + td * 3 + 1];
            float v2 = Vs[kk * CS + td * 3 + 2];
            float pa[4] = {p.x, p.y, p.z, p.w};
#pragma unroll
            for (int i = 0; i < 4; i++) {
                acc[i][0] += pa[i] * v0;
                acc[i][1] += pa[i] * v1;
                acc[i][2] += pa[i] * v2;
            }
        }
        __syncthreads();
    }
#pragma unroll
    for (int i = 0; i < 4; i++) {
        float* dst = g_X + ((b * NN + q0 + tq * 4 + i) * CS) + td * 3;
        dst[0] = acc[i][0]; dst[1] = acc[i][1]; dst[2] = acc[i][2];
    }
}

// ---------------- conv3d 3x3x3 (96 -> 96), SAME padding --------------------
// grid (cog=6, d=16, b=2), 256 threads = 16h x 16w, 16 co per thread.
__global__ __launch_bounds__(256) void k_conv3d(
    const float* __restrict__ w3, const float* __restrict__ b3)
{
    __shared__ __align__(16) float in_s[3 * 18 * 18];
    __shared__ __align__(16) float ws[27][16];      // [tap][co]

    int cog = blockIdx.x, d = blockIdx.y, b = blockIdx.z;
    int t = threadIdx.x, h = t >> 4, w = t & 15;

    float acc[16];
#pragma unroll
    for (int co = 0; co < 16; co++) acc[co] = b3[cog * 16 + co];

    for (int ci = 0; ci < CY; ci++) {
        const float* src = g_Ype + (b * CY + ci) * NN;
        for (int i = t; i < 3 * 324; i += 256) {
            int dd = i / 324, rem = i - dd * 324, r = rem / 18, c = rem - r * 18;
            int z = d + dd - 1, y = r - 1, x = c - 1;
            float v = 0.f;
            if (z >= 0 && z < 16 && y >= 0 && y < 16 && x >= 0 && x < 16)
                v = src[z * 256 + y * 16 + x];
            in_s[i] = v;
        }
        // FIX (R1): 432 weight slots but only 256 threads -> must stride.
        for (int i = t; i < 16 * 27; i += 256) {
            int tap = i % 27, co = i / 27;
            ws[tap][co] = w3[(cog * 16 + co) * (CY * 27) + ci * 27 + tap];
        }
        __syncthreads();

        float in_r[27];
#pragma unroll
        for (int dd = 0; dd < 3; dd++)
#pragma unroll
            for (int dy = 0; dy < 3; dy++)
#pragma unroll
                for (int dx = 0; dx < 3; dx++)
                    in_r[dd*9+dy*3+dx] = in_s[dd*324 + (h+dy)*18 + (w+dx)];

#pragma unroll
        for (int tap = 0; tap < 27; tap++) {
            float x = in_r[tap];
            float4 w0 = *(const float4*)&ws[tap][0];
            float4 w1 = *(const float4*)&ws[tap][4];
            float4 w2 = *(const float4*)&ws[tap][8];
            float4 w3v= *(const float4*)&ws[tap][12];
            acc[0]+=w0.x*x; acc[1]+=w0.y*x; acc[2]+=w0.z*x; acc[3]+=w0.w*x;
            acc[4]+=w1.x*x; acc[5]+=w1.y*x; acc[6]+=w1.z*x; acc[7]+=w1.w*x;
            acc[8]+=w2.x*x; acc[9]+=w2.y*x; acc[10]+=w2.z*x; acc[11]+=w2.w*x;
            acc[12]+=w3v.x*x; acc[13]+=w3v.y*x; acc[14]+=w3v.z*x; acc[15]+=w3v.w*x;
        }
        __syncthreads();
    }
    int n = d * 256 + t;
#pragma unroll
    for (int co = 0; co < 16; co++)
        g_Y3[(b * CY + cog * 16 + co) * NN + n] = acc[co];
}

// ---------------- Z output: bn_relu(X @ w_o) * Spe -> out[:, 0:48] ---------
__global__ __launch_bounds__(256) void k_zout(
    const float* __restrict__ w_o, const float* __restrict__ b_o,
    const float* __restrict__ g_o, const float* __restrict__ be_o,
    float* __restrict__ out)
{
    __shared__ float xs[CS * 64];   // [d][n]
    __shared__ float wot[CS * CS];  // wot[d*48+e] = w_o[e*48+d]

    int b = blockIdx.y, n0 = blockIdx.x * 64, t = threadIdx.x;
    for (int i = t; i < CS * CS; i += 256) {
        int e = i % CS, d = i / CS;
        wot[i] = w_o[e * CS + d];
    }
    {
        int n = t & 63, v = t >> 6;
        const float* src = g_X + ((b * NN + n0 + n) * CS);
#pragma unroll
        for (int r = 0; r < 3; r++) {
            int dv = v + r * 4;
            float4 x = *(const float4*)&src[dv * 4];
            xs[(dv*4+0)*64+n] = x.x; xs[(dv*4+1)*64+n] = x.y;
            xs[(dv*4+2)*64+n] = x.z; xs[(dv*4+3)*64+n] = x.w;
        }
    }
    __syncthreads();

    int n = t & 63, eg = t >> 6;
    float acc[12];
#pragma unroll
    for (int j = 0; j < 12; j++) acc[j] = 0.f;
    for (int d = 0; d < CS; d++) {
        float x = xs[d * 64 + n];
#pragma unroll
        for (int v = 0; v < 3; v++) {
            float4 w4 = *(const float4*)&wot[d * CS + eg * 12 + v * 4];
            acc[v*4+0] += w4.x * x; acc[v*4+1] += w4.y * x;
            acc[v*4+2] += w4.z * x; acc[v*4+3] += w4.w * x;
        }
    }
    float inv = rsqrtf(1.f + 1e-5f);
#pragma unroll
    for (int j = 0; j < 12; j++) {
        int e = eg * 12 + j;
        float y = (acc[j] + b_o[e]) * (g_o[e] * inv) + be_o[e];
        y = fmaxf(y, 0.f);
        float z = y * g_Spe[(b * CS + e) * NN + n0 + n];
        out[(b * 96 + e) * NN + n0 + n] = z;
    }
}

// ---------------- Y2 output: bn_relu(Y3 @ w_y2) -> out[:, 48:96] -----------
__global__ __launch_bounds__(256) void k_y2out(
    const float* __restrict__ w_y2, const float* __restrict__ b_y2,
    const float* __restrict__ g_y2, const float* __restrict__ be_y2,
    float* __restrict__ out)
{
    __shared__ float in_s[CY * 64];  // [c][n]
    __shared__ float wt[CY * CS];    // wt[c*48+e] = w_y2[e*96+c]

    int b = blockIdx.y, n0 = blockIdx.x * 64, t = threadIdx.x;
    for (int i = t; i < CY * CS; i += 256) {
        int e = i % CS, c = i / CS;
        wt[i] = w_y2[e * CY + c];
    }
    const float* src = g_Y3 + (b * CY) * NN + n0;
    for (int i = t; i < CY * 64; i += 256) {
        int c = i >> 6, n = i & 63;
        in_s[i] = src[c * NN + n];
    }
    __syncthreads();

    int n = t & 63, eg = t >> 6;
    float acc[12];
#pragma unroll
    for (int j = 0; j < 12; j++) acc[j] = 0.f;
    for (int c = 0; c < CY; c++) {
        float x = in_s[c * 64 + n];
#pragma unroll
        for (int v = 0; v < 3; v++) {
            float4 w4 = *(const float4*)&wt[c * CS + eg * 12 + v * 4];
            acc[v*4+0] += w4.x * x; acc[v*4+1] += w4.y * x;
            acc[v*4+2] += w4.z * x; acc[v*4+3] += w4.w * x;
        }
    }
    float inv = rsqrtf(1.f + 1e-5f);
#pragma unroll
    for (int j = 0; j < 12; j++) {
        int e = eg * 12 + j;
        float y = (acc[j] + b_y2[e]) * (g_y2[e] * inv) + be_y2[e];
        out[(b * 96 + 48 + e) * NN + n0 + n] = fmaxf(y, 0.f);
    }
}

// ---------------- launch ----------------------------------------------------
extern "C" void kernel_launch(void* const* d_in, const int* in_sizes, int n_in,
                              void* d_out, int out_size)
{
    const float* Y    = (const float*)d_in[0];
    const float* S    = (const float*)d_in[1];
    const float* w_s  = (const float*)d_in[2];
    const float* b_s  = (const float*)d_in[3];
    const float* g_s  = (const float*)d_in[4];
    const float* be_s = (const float*)d_in[5];
    const float* w_y  = (const float*)d_in[6];
    const float* b_y  = (const float*)d_in[7];
    const float* g_y  = (const float*)d_in[8];
    const float* be_y = (const float*)d_in[9];
    const float* Wq   = (const float*)d_in[10];
    const float* Wk   = (const float*)d_in[11];
    const float* Wv   = (const float*)d_in[12];
    const float* w_o  = (const float*)d_in[13];
    const float* b_o  = (const float*)d_in[14];
    const float* g_o  = (const float*)d_in[15];
    const float* be_o = (const float*)d_in[16];
    const float* w3   = (const float*)d_in[17];
    const float* b3   = (const float*)d_in[18];
    const float* w_y2 = (const float*)d_in[19];
    const float* b_y2 = (const float*)d_in[20];
    const float* g_y2 = (const float*)d_in[21];
    const float* be_y2= (const float*)d_in[22];
    float* out = (float*)d_out;

    k_addpe_s<<<(BB*CS*NN + 255)/256, 256>>>(S);
    k_addpe_y<<<(BB*CY*NN + 255)/256, 256>>>(Y);

    k_proj_sv<<<dim3(NN/64, BB), 256>>>(w_s, b_s, g_s, be_s, Wv);
    k_proj_y1<<<dim3(NN/64, BB), 256>>>(w_y, b_y, g_y, be_y);
    k_qk     <<<dim3(NN/64, BB), 256>>>(Wq, Wk);

    k_logits  <<<dim3(NN/64, NN/64, BB), 256>>>();
    k_colstats<<<dim3(NN, BB), 256>>>();
    k_av      <<<dim3(NN/64, BB), 256>>>();

    k_conv3d<<<dim3(CY/16, 16, BB), 256>>>(w3, b3);

    k_zout <<<dim3(NN/64, BB), 256>>>(w_o, b_o, g_o, be_o, out);
    k_y2out<<<dim3(NN/64, BB), 256>>>(w_y2, b_y2, g_y2, be_y2, out);
}

// round 4
// speedup vs baseline: 1.0070x; 1.0070x over previous
#include <cuda_runtime.h>
#include <math.h>

#define BB 2
#define CY 96
#define CS 48
#define NN 4096
#define SCALE 0.14433756729740643f  /* 48^-0.5 */

// ---------------- scratch (device globals: no runtime allocation) ----------
__device__ float g_Spe[BB*CS*NN];
__device__ float g_Ype[BB*CY*NN];
__device__ float g_Y1 [BB*NN*CS];
__device__ float g_Q  [BB*NN*CS];
__device__ float g_K  [BB*NN*CS];
__device__ float g_V  [BB*NN*CS];
__device__ float g_X  [BB*NN*CS];
__device__ float g_Y3 [BB*CY*NN];
__device__ float g_m  [BB*NN];
__device__ float g_iz [BB*NN];
__device__ float g_Lt [(size_t)BB*NN*NN];   // 128 MB: logits transposed [b][k][q]

// ---------------- positional encoding + add --------------------------------
// pe[ch, d, h, w]:  c = C/3 (exact here). blk = ch/c, t = ch%c.
//   blk 0,1 -> emb(h)[t]   (faithful torch broadcasting quirk: both x and y
//   blocks read the *h* index since x==y==16)
//   blk 2   -> emb(w)[t]
//   emb(n)[t] = t < c/2 ? sin(n*10000^{-2t/c}) : cos(n*10000^{-2(t-c/2)/c})
__device__ __forceinline__ float pe_val(int ch, int h, int w, int c) {
    int blk = ch / c, t = ch - blk * c;
    int pos = (blk < 2) ? h : w;
    int half = c >> 1;
    float val;
    if (t < half) {
        float invf = powf(10000.f, -2.f * (float)t / (float)c);
        val = sinf((float)pos * invf);
    } else {
        float invf = powf(10000.f, -2.f * (float)(t - half) / (float)c);
        val = cosf((float)pos * invf);
    }
    return val;
}

__global__ void k_addpe_s(const float* __restrict__ S) {
    int i = blockIdx.x * blockDim.x + threadIdx.x;
    if (i >= BB * CS * NN) return;
    int n = i & (NN - 1);
    int ch = (i >> 12) % CS;
    int h = (n >> 4) & 15, w = n & 15;
    g_Spe[i] = S[i] + pe_val(ch, h, w, 16);
}

__global__ void k_addpe_y(const float* __restrict__ Y) {
    int i = blockIdx.x * blockDim.x + threadIdx.x;
    if (i >= BB * CY * NN) return;
    int n = i & (NN - 1);
    int ch = (i >> 12) % CY;
    int h = (n >> 4) & 15, w = n & 15;
    g_Ype[i] = Y[i] + pe_val(ch, h, w, 32);
}

// ---------------- S1 projection fused with V = S1 @ Wv ---------------------
// block: (n-tile of 64, b). 256 threads. thread -> (n = t&63, eg = t>>6),
// each handles 12 output channels.
__global__ __launch_bounds__(256) void k_proj_sv(
    const float* __restrict__ w_s, const float* __restrict__ b_s,
    const float* __restrict__ g_s, const float* __restrict__ be_s,
    const float* __restrict__ Wv)
{
    __shared__ float in_s[CS * 64];         // [c][n]
    __shared__ float wt[CS * CS];           // wt[c*48+e] = w_s[e*48+c]
    __shared__ float wv[CS * CS];           // natural [d][e]
    __shared__ float s1[64 * 49];           // [n][d], pad 49

    int b = blockIdx.y, n0 = blockIdx.x * 64, t = threadIdx.x;
    for (int i = t; i < CS * CS; i += 256) {
        int e = i % CS, c = i / CS;
        wt[i] = w_s[e * CS + c];
        wv[i] = Wv[i];
    }
    const float* src = g_Spe + (b * CS) * NN + n0;
    for (int i = t; i < CS * 64; i += 256) {
        int c = i >> 6, n = i & 63;
        in_s[i] = src[c * NN + n];
    }
    __syncthreads();

    int n = t & 63, eg = t >> 6;
    float acc[12];
#pragma unroll
    for (int j = 0; j < 12; j++) acc[j] = 0.f;
    for (int c = 0; c < CS; c++) {
        float x = in_s[c * 64 + n];
#pragma unroll
        for (int v = 0; v < 3; v++) {
            float4 w4 = *(const float4*)&wt[c * CS + eg * 12 + v * 4];
            acc[v*4+0] += w4.x * x; acc[v*4+1] += w4.y * x;
            acc[v*4+2] += w4.z * x; acc[v*4+3] += w4.w * x;
        }
    }
    float inv = rsqrtf(1.f + 1e-5f);
#pragma unroll
    for (int j = 0; j < 12; j++) {
        int e = eg * 12 + j;
        float y = (acc[j] + b_s[e]) * (g_s[e] * inv) + be_s[e];
        s1[n * 49 + e] = fmaxf(y, 0.f);
    }
    __syncthreads();

#pragma unroll
    for (int j = 0; j < 12; j++) acc[j] = 0.f;
    for (int d = 0; d < CS; d++) {
        float x = s1[n * 49 + d];
#pragma unroll
        for (int v = 0; v < 3; v++) {
            float4 w4 = *(const float4*)&wv[d * CS + eg * 12 + v * 4];
            acc[v*4+0] += w4.x * x; acc[v*4+1] += w4.y * x;
            acc[v*4+2] += w4.z * x; acc[v*4+3] += w4.w * x;
        }
    }
    float* dst = g_V + ((b * NN + n0 + n) * CS) + eg * 12;
#pragma unroll
    for (int v = 0; v < 3; v++)
        *(float4*)&dst[v * 4] = make_float4(acc[v*4], acc[v*4+1], acc[v*4+2], acc[v*4+3]);
}

// ---------------- Y1 projection (96 -> 48) ---------------------------------
__global__ __launch_bounds__(256) void k_proj_y1(
    const float* __restrict__ w_y, const float* __restrict__ b_y,
    const float* __restrict__ g_y, const float* __restrict__ be_y)
{
    __shared__ float in_s[CY * 64];     // [c][n]
    __shared__ float wt[CY * CS];       // wt[c*48+e] = w_y[e*96+c]

    int b = blockIdx.y, n0 = blockIdx.x * 64, t = threadIdx.x;
    for (int i = t; i < CY * CS; i += 256) {
        int e = i % CS, c = i / CS;
        wt[i] = w_y[e * CY + c];
    }
    const float* src = g_Ype + (b * CY) * NN + n0;
    for (int i = t; i < CY * 64; i += 256) {
        int c = i >> 6, n = i & 63;
        in_s[i] = src[c * NN + n];
    }
    __syncthreads();

    int n = t & 63, eg = t >> 6;
    float acc[12];
#pragma unroll
    for (int j = 0; j < 12; j++) acc[j] = 0.f;
    for (int c = 0; c < CY; c++) {
        float x = in_s[c * 64 + n];
#pragma unroll
        for (int v = 0; v < 3; v++) {
            float4 w4 = *(const float4*)&wt[c * CS + eg * 12 + v * 4];
            acc[v*4+0] += w4.x * x; acc[v*4+1] += w4.y * x;
            acc[v*4+2] += w4.z * x; acc[v*4+3] += w4.w * x;
        }
    }
    float inv = rsqrtf(1.f + 1e-5f);
    float* dst = g_Y1 + ((b * NN + n0 + n) * CS) + eg * 12;
#pragma unroll
    for (int j = 0; j < 12; j++) {
        int e = eg * 12 + j;
        float y = (acc[j] + b_y[e]) * (g_y[e] * inv) + be_y[e];
        dst[j] = fmaxf(y, 0.f);
    }
}

// ---------------- Q = Y1 @ Wq, K = Y1 @ Wk ---------------------------------
__global__ __launch_bounds__(256) void k_qk(
    const float* __restrict__ Wq, const float* __restrict__ Wk)
{
    __shared__ float y1[64 * 49];       // [n][d]
    __shared__ float wq[CS * CS];       // natural [d][e]
    __shared__ float wk[CS * CS];

    int b = blockIdx.y, n0 = blockIdx.x * 64, t = threadIdx.x;
    for (int i = t; i < CS * CS; i += 256) { wq[i] = Wq[i]; wk[i] = Wk[i]; }
    const float* src = g_Y1 + (b * NN + n0) * CS;
    for (int i = t; i < 64 * CS; i += 256) {
        int n = i / CS, d = i % CS;
        y1[n * 49 + d] = src[i];
    }
    __syncthreads();

    int n = t & 63, eg = t >> 6;
    float aq[12], ak[12];
#pragma unroll
    for (int j = 0; j < 12; j++) { aq[j] = 0.f; ak[j] = 0.f; }
    for (int d = 0; d < CS; d++) {
        float x = y1[n * 49 + d];
#pragma unroll
        for (int v = 0; v < 3; v++) {
            float4 q4 = *(const float4*)&wq[d * CS + eg * 12 + v * 4];
            float4 k4 = *(const float4*)&wk[d * CS + eg * 12 + v * 4];
            aq[v*4+0] += q4.x * x; aq[v*4+1] += q4.y * x;
            aq[v*4+2] += q4.z * x; aq[v*4+3] += q4.w * x;
            ak[v*4+0] += k4.x * x; ak[v*4+1] += k4.y * x;
            ak[v*4+2] += k4.z * x; ak[v*4+3] += k4.w * x;
        }
    }
    float* dq = g_Q + ((b * NN + n0 + n) * CS) + eg * 12;
    float* dk = g_K + ((b * NN + n0 + n) * CS) + eg * 12;
#pragma unroll
    for (int v = 0; v < 3; v++) {
        *(float4*)&dq[v * 4] = make_float4(aq[v*4], aq[v*4+1], aq[v*4+2], aq[v*4+3]);
        *(float4*)&dk[v * 4] = make_float4(ak[v*4], ak[v*4+1], ak[v*4+2], ak[v*4+3]);
    }
}

// ---------------- logits: Lt[b][k][q] = SCALE * Q[q]·K[k] ------------------
// 64x64 output tile, 256 threads, 4x4 micro-tile, d=48 inner.
__global__ __launch_bounds__(256) void k_logits() {
    __shared__ float Qs[CS * 64];   // [d][q]
    __shared__ float Ks[CS * 64];   // [d][k]

    int q0 = blockIdx.x * 64, k0 = blockIdx.y * 64, b = blockIdx.z;
    int t = threadIdx.x;
    {
        int n = t & 63, v = t >> 6;
        const float* sq = g_Q + ((b * NN + q0 + n) * CS);
        const float* sk = g_K + ((b * NN + k0 + n) * CS);
#pragma unroll
        for (int r = 0; r < 3; r++) {
            int dv = v + r * 4;
            float4 x = *(const float4*)&sq[dv * 4];
            Qs[(dv*4+0)*64+n] = x.x; Qs[(dv*4+1)*64+n] = x.y;
            Qs[(dv*4+2)*64+n] = x.z; Qs[(dv*4+3)*64+n] = x.w;
            float4 y = *(const float4*)&sk[dv * 4];
            Ks[(dv*4+0)*64+n] = y.x; Ks[(dv*4+1)*64+n] = y.y;
            Ks[(dv*4+2)*64+n] = y.z; Ks[(dv*4+3)*64+n] = y.w;
        }
    }
    __syncthreads();

    int tq = t & 15, tk = t >> 4;
    float acc[4][4];
#pragma unroll
    for (int i = 0; i < 4; i++)
#pragma unroll
        for (int j = 0; j < 4; j++) acc[i][j] = 0.f;

    for (int d = 0; d < CS; d++) {
        float4 kk = *(const float4*)&Ks[d * 64 + tk * 4];
        float4 qq = *(const float4*)&Qs[d * 64 + tq * 4];
        float ka[4] = {kk.x, kk.y, kk.z, kk.w};
        float qa[4] = {qq.x, qq.y, qq.z, qq.w};
#pragma unroll
        for (int i = 0; i < 4; i++)
#pragma unroll
            for (int j = 0; j < 4; j++) acc[i][j] += ka[i] * qa[j];
    }
#pragma unroll
    for (int i = 0; i < 4; i++) {
        size_t row = (size_t)(b * NN + k0 + tk * 4 + i) * NN + q0 + tq * 4;
        *(float4*)&g_Lt[row] = make_float4(acc[i][0]*SCALE, acc[i][1]*SCALE,
                                           acc[i][2]*SCALE, acc[i][3]*SCALE);
    }
}

// ---------------- column stats: online max & sumexp over q -----------------
__global__ __launch_bounds__(256) void k_colstats() {
    int k = blockIdx.x, b = blockIdx.y;
    const float* row = g_Lt + (size_t)(b * NN + k) * NN;
    float m = -1e30f, s = 0.f;
    for (int q = threadIdx.x; q < NN; q += 256) {
        float v = row[q];
        if (v > m) { s = s * __expf(m - v) + 1.f; m = v; }
        else       { s += __expf(v - m); }
    }
#pragma unroll
    for (int o = 16; o; o >>= 1) {
        float m2 = __shfl_xor_sync(0xffffffffu, m, o);
        float s2 = __shfl_xor_sync(0xffffffffu, s, o);
        float M = fmaxf(m, m2);
        s = s * __expf(m - M) + s2 * __expf(m2 - M);
        m = M;
    }
    __shared__ float sm[8], ss[8];
    int w = threadIdx.x >> 5, l = threadIdx.x & 31;
    if (l == 0) { sm[w] = m; ss[w] = s; }
    __syncthreads();
    if (threadIdx.x == 0) {
        float M = sm[0], Ssum = ss[0];
#pragma unroll
        for (int i = 1; i < 8; i++) {
            float M2 = fmaxf(M, sm[i]);
            Ssum = Ssum * __expf(M - M2) + ss[i] * __expf(sm[i] - M2);
            M = M2;
        }
        g_m [b * NN + k] = M;
        g_iz[b * NN + k] = 1.f / Ssum;
    }
}

// ---------------- AV: x[q][d] = sum_k exp(Lt[k][q]-m[k])*izk * V[k][d] -----
__global__ __launch_bounds__(256) void k_av() {
    __shared__ float Ps[64 * 64];   // [k][q]
    __shared__ float Vs[64 * CS];   // [k][d]

    int q0 = blockIdx.x * 64, b = blockIdx.y, t = threadIdx.x;
    int tq = t & 15, td = t >> 4;
    float acc[4][3];
#pragma unroll
    for (int i = 0; i < 4; i++)
#pragma unroll
        for (int j = 0; j < 3; j++) acc[i][j] = 0.f;

    int kl = t >> 2, qb = (t & 3) * 16;
    for (int k0 = 0; k0 < NN; k0 += 64) {
        float mk = g_m [b * NN + k0 + kl];
        float zk = g_iz[b * NN + k0 + kl];
        const float* srcL = g_Lt + (size_t)(b * NN + k0 + kl) * NN + q0 + qb;
#pragma unroll
        for (int r = 0; r < 4; r++) {
            float4 x = *(const float4*)&srcL[r * 4];
            float* p = &Ps[kl * 64 + qb + r * 4];
            p[0] = __expf(x.x - mk) * zk; p[1] = __expf(x.y - mk) * zk;
            p[2] = __expf(x.z - mk) * zk; p[3] = __expf(x.w - mk) * zk;
        }
        const float* srcV = g_V + ((b * NN + k0 + kl) * CS) + (t & 3) * 12;
        float* dv = &Vs[kl * CS + (t & 3) * 12];
#pragma unroll
        for (int r = 0; r < 3; r++)
            *(float4*)&dv[r * 4] = *(const float4*)&srcV[r * 4];
        __syncthreads();

        for (int kk = 0; kk < 64; kk++) {
            float4 p = *(const float4*)&Ps[kk * 64 + tq * 4];
            float v0 = Vs[kk * CS + td * 3 + 0];
            float v1 = Vs[kk * CS + td * 3 + 1];
            float v2 = Vs[kk * CS + td * 3 + 2];
            float pa[4] = {p.x, p.y, p.z, p.w};
#pragma unroll
            for (int i = 0; i < 4; i++) {
                acc[i][0] += pa[i] * v0;
                acc[i][1] += pa[i] * v1;
                acc[i][2] += pa[i] * v2;
            }
        }
        __syncthreads();
    }
#pragma unroll
    for (int i = 0; i < 4; i++) {
        float* dst = g_X + ((b * NN + q0 + tq * 4 + i) * CS) + td * 3;
        dst[0] = acc[i][0]; dst[1] = acc[i][1]; dst[2] = acc[i][2];
    }
}

// ---------------- conv3d 3x3x3 (96 -> 96), SAME padding --------------------
// grid (cog=6, d=16, b=2), 256 threads = 16h x 16w, 16 co per thread.
__global__ __launch_bounds__(256) void k_conv3d(
    const float* __restrict__ w3, const float* __restrict__ b3)
{
    __shared__ __align__(16) float in_s[3 * 18 * 18];
    __shared__ __align__(16) float ws[27][16];      // [tap][co]

    int cog = blockIdx.x, d = blockIdx.y, b = blockIdx.z;
    int t = threadIdx.x, h = t >> 4, w = t & 15;

    float acc[16];
#pragma unroll
    for (int co = 0; co < 16; co++) acc[co] = b3[cog * 16 + co];

    for (int ci = 0; ci < CY; ci++) {
        const float* src = g_Ype + (b * CY + ci) * NN;
        for (int i = t; i < 3 * 324; i += 256) {
            int dd = i / 324, rem = i - dd * 324, r = rem / 18, c = rem - r * 18;
            int z = d + dd - 1, y = r - 1, x = c - 1;
            float v = 0.f;
            if (z >= 0 && z < 16 && y >= 0 && y < 16 && x >= 0 && x < 16)
                v = src[z * 256 + y * 16 + x];
            in_s[i] = v;
        }
        // FIX (R1): 432 weight slots but only 256 threads -> must stride.
        for (int i = t; i < 16 * 27; i += 256) {
            int tap = i % 27, co = i / 27;
            ws[tap][co] = w3[(cog * 16 + co) * (CY * 27) + ci * 27 + tap];
        }
        __syncthreads();

        float in_r[27];
#pragma unroll
        for (int dd = 0; dd < 3; dd++)
#pragma unroll
            for (int dy = 0; dy < 3; dy++)
#pragma unroll
                for (int dx = 0; dx < 3; dx++)
                    in_r[dd*9+dy*3+dx] = in_s[dd*324 + (h+dy)*18 + (w+dx)];

#pragma unroll
        for (int tap = 0; tap < 27; tap++) {
            float x = in_r[tap];
            float4 w0 = *(const float4*)&ws[tap][0];
            float4 w1 = *(const float4*)&ws[tap][4];
            float4 w2 = *(const float4*)&ws[tap][8];
            float4 w3v= *(const float4*)&ws[tap][12];
            acc[0]+=w0.x*x; acc[1]+=w0.y*x; acc[2]+=w0.z*x; acc[3]+=w0.w*x;
            acc[4]+=w1.x*x; acc[5]+=w1.y*x; acc[6]+=w1.z*x; acc[7]+=w1.w*x;
            acc[8]+=w2.x*x; acc[9]+=w2.y*x; acc[10]+=w2.z*x; acc[11]+=w2.w*x;
            acc[12]+=w3v.x*x; acc[13]+=w3v.y*x; acc[14]+=w3v.z*x; acc[15]+=w3v.w*x;
        }
        __syncthreads();
    }
    int n = d * 256 + t;
#pragma unroll
    for (int co = 0; co < 16; co++)
        g_Y3[(b * CY + cog * 16 + co) * NN + n] = acc[co];
}

// ---------------- Z output: bn_relu(X @ w_o) * Spe -> out[:, 0:48] ---------
__global__ __launch_bounds__(256) void k_zout(
    const float* __restrict__ w_o, const float* __restrict__ b_o,
    const float* __restrict__ g_o, const float* __restrict__ be_o,
    float* __restrict__ out)
{
    __shared__ float xs[CS * 64];   // [d][n]
    __shared__ float wot[CS * CS];  // wot[d*48+e] = w_o[e*48+d]

    int b = blockIdx.y, n0 = blockIdx.x * 64, t = threadIdx.x;
    for (int i = t; i < CS * CS; i += 256) {
        int e = i % CS, d = i / CS;
        wot[i] = w_o[e * CS + d];
    }
    {
        int n = t & 63, v = t >> 6;
        const float* src = g_X + ((b * NN + n0 + n) * CS);
#pragma unroll
        for (int r = 0; r < 3; r++) {
            int dv = v + r * 4;
            float4 x = *(const float4*)&src[dv * 4];
            xs[(dv*4+0)*64+n] = x.x; xs[(dv*4+1)*64+n] = x.y;
            xs[(dv*4+2)*64+n] = x.z; xs[(dv*4+3)*64+n] = x.w;
        }
    }
    __syncthreads();

    int n = t & 63, eg = t >> 6;
    float acc[12];
#pragma unroll
    for (int j = 0; j < 12; j++) acc[j] = 0.f;
    for (int d = 0; d < CS; d++) {
        float x = xs[d * 64 + n];
#pragma unroll
        for (int v = 0; v < 3; v++) {
            float4 w4 = *(const float4*)&wot[d * CS + eg * 12 + v * 4];
            acc[v*4+0] += w4.x * x; acc[v*4+1] += w4.y * x;
            acc[v*4+2] += w4.z * x; acc[v*4+3] += w4.w * x;
        }
    }
    float inv = rsqrtf(1.f + 1e-5f);
#pragma unroll
    for (int j = 0; j < 12; j++) {
        int e = eg * 12 + j;
        float y = (acc[j] + b_o[e]) * (g_o[e] * inv) + be_o[e];
        y = fmaxf(y, 0.f);
        float z = y * g_Spe[(b * CS + e) * NN + n0 + n];
        out[(b * 96 + e) * NN + n0 + n] = z;
    }
}

// ---------------- Y2 output: bn_relu(Y3 @ w_y2) -> out[:, 48:96] -----------
__global__ __launch_bounds__(256) void k_y2out(
    const float* __restrict__ w_y2, const float* __restrict__ b_y2,
    const float* __restrict__ g_y2, const float* __restrict__ be_y2,
    float* __restrict__ out)
{
    __shared__ float in_s[CY * 64];  // [c][n]
    __shared__ float wt[CY * CS];    // wt[c*48+e] = w_y2[e*96+c]

    int b = blockIdx.y, n0 = blockIdx.x * 64, t = threadIdx.x;
    for (int i = t; i < CY * CS; i += 256) {
        int e = i % CS, c = i / CS;
        wt[i] = w_y2[e * CY + c];
    }
    const float* src = g_Y3 + (b * CY) * NN + n0;
    for (int i = t; i < CY * 64; i += 256) {
        int c = i >> 6, n = i & 63;
        in_s[i] = src[c * NN + n];
    }
    __syncthreads();

    int n = t & 63, eg = t >> 6;
    float acc[12];
#pragma unroll
    for (int j = 0; j < 12; j++) acc[j] = 0.f;
    for (int c = 0; c < CY; c++) {
        float x = in_s[c * 64 + n];
#pragma unroll
        for (int v = 0; v < 3; v++) {
            float4 w4 = *(const float4*)&wt[c * CS + eg * 12 + v * 4];
            acc[v*4+0] += w4.x * x; acc[v*4+1] += w4.y * x;
            acc[v*4+2] += w4.z * x; acc[v*4+3] += w4.w * x;
        }
    }
    float inv = rsqrtf(1.f + 1e-5f);
#pragma unroll
    for (int j = 0; j < 12; j++) {
        int e = eg * 12 + j;
        float y = (acc[j] + b_y2[e]) * (g_y2[e] * inv) + be_y2[e];
        out[(b * 96 + 48 + e) * NN + n0 + n] = fmaxf(y, 0.f);
    }
}

// ---------------- launch ----------------------------------------------------
extern "C" void kernel_launch(void* const* d_in, const int* in_sizes, int n_in,
                              void* d_out, int out_size)
{
    const float* Y    = (const float*)d_in[0];
    const float* S    = (const float*)d_in[1];
    const float* w_s  = (const float*)d_in[2];
    const float* b_s  = (const float*)d_in[3];
    const float* g_s  = (const float*)d_in[4];
    const float* be_s = (const float*)d_in[5];
    const float* w_y  = (const float*)d_in[6];
    const float* b_y  = (const float*)d_in[7];
    const float* g_y  = (const float*)d_in[8];
    const float* be_y = (const float*)d_in[9];
    const float* Wq   = (const float*)d_in[10];
    const float* Wk   = (const float*)d_in[11];
    const float* Wv   = (const float*)d_in[12];
    const float* w_o  = (const float*)d_in[13];
    const float* b_o  = (const float*)d_in[14];
    const float* g_o  = (const float*)d_in[15];
    const float* be_o = (const float*)d_in[16];
    const float* w3   = (const float*)d_in[17];
    const float* b3   = (const float*)d_in[18];
    const float* w_y2 = (const float*)d_in[19];
    const float* b_y2 = (const float*)d_in[20];
    const float* g_y2 = (const float*)d_in[21];
    const float* be_y2= (const float*)d_in[22];
    float* out = (float*)d_out;

    k_addpe_s<<<(BB*CS*NN + 255)/256, 256>>>(S);
    k_addpe_y<<<(BB*CY*NN + 255)/256, 256>>>(Y);

    k_proj_sv<<<dim3(NN/64, BB), 256>>>(w_s, b_s, g_s, be_s, Wv);
    k_proj_y1<<<dim3(NN/64, BB), 256>>>(w_y, b_y, g_y, be_y);
    k_qk     <<<dim3(NN/64, BB), 256>>>(Wq, Wk);

    k_logits  <<<dim3(NN/64, NN/64, BB), 256>>>();
    k_colstats<<<dim3(NN, BB), 256>>>();
    k_av      <<<dim3(NN/64, BB), 256>>>();

    k_conv3d<<<dim3(CY/16, 16, BB), 256>>>(w3, b3);

    k_zout <<<dim3(NN/64, BB), 256>>>(w_o, b_o, g_o, be_o, out);
    k_y2out<<<dim3(NN/64, BB), 256>>>(w_y2, b_y2, g_y2, be_y2, out);
}

// round 5
// speedup vs baseline: 1.8728x; 1.8597x over previous
#include <cuda_runtime.h>
#include <cuda_bf16.h>
#include <math.h>
#include <stdint.h>

#define BB 2
#define CY 96
#define CS 48
#define NN 4096
#define SCALE 0.14433756729740643f  /* 48^-0.5 */

// ---------------- scratch (device globals: no runtime allocation) ----------
__device__ __align__(16) float g_Spe[BB*CS*NN];
__device__ __align__(16) float g_Ype[BB*CY*NN];
__device__ __align__(16) float g_Y1 [BB*NN*CS];
__device__ __align__(16) float g_V  [BB*NN*CS];
__device__ __align__(16) __nv_bfloat16 g_Qh[BB*NN*CS], g_Ql[BB*NN*CS];
__device__ __align__(16) __nv_bfloat16 g_Kh[BB*NN*CS], g_Kl[BB*NN*CS];
__device__ __align__(16) __nv_bfloat16 g_Vth[BB*CS*NN], g_Vtl[BB*CS*NN];
__device__ __align__(16) float g_L[(size_t)BB*NN*NN];   // 128 MB expL [b][q][k]
__device__ __align__(16) float g_psum[BB*32*NN];        // per-qblock column sums
__device__ __align__(16) float g_Xp[4*BB*NN*CS];        // AV partials (4 k-chunks)
__device__ __align__(16) float g_Y3p[2*BB*CY*NN];       // conv partials (2 ci halves)
__device__ __align__(16) float g_peS[CS*256];
__device__ __align__(16) float g_peY[CY*256];

// ---------------- helpers ---------------------------------------------------
__device__ __forceinline__ void mma16816(float* c, const uint32_t* a, const uint32_t* b) {
    asm volatile(
        "mma.sync.aligned.m16n8k16.row.col.f32.bf16.bf16.f32 "
        "{%0,%1,%2,%3}, {%4,%5,%6,%7}, {%8,%9}, {%0,%1,%2,%3};\n"
        : "+f"(c[0]), "+f"(c[1]), "+f"(c[2]), "+f"(c[3])
        : "r"(a[0]), "r"(a[1]), "r"(a[2]), "r"(a[3]), "r"(b[0]), "r"(b[1]));
}

__device__ __forceinline__ uint32_t bf2u(__nv_bfloat16 a, __nv_bfloat16 b) {
    __nv_bfloat162 v(a, b);
    return *reinterpret_cast<uint32_t*>(&v);
}

__device__ __forceinline__ void fma2(unsigned long long& d, unsigned long long a,
                                     unsigned long long b) {
    asm("fma.rn.f32x2 %0, %1, %2, %0;" : "+l"(d) : "l"(a), "l"(b));
}

// ---------------- positional encoding tables --------------------------------
__device__ __forceinline__ float pe_val(int ch, int h, int w, int c) {
    int blk = ch / c, t = ch - blk * c;
    int pos = (blk < 2) ? h : w;    // torch broadcast quirk: x & y blocks both use h
    int half = c >> 1;
    if (t < half) {
        float invf = powf(10000.f, -2.f * (float)t / (float)c);
        return sinf((float)pos * invf);
    } else {
        float invf = powf(10000.f, -2.f * (float)(t - half) / (float)c);
        return cosf((float)pos * invf);
    }
}

__global__ void k_petab() {
    int i = blockIdx.x * 256 + threadIdx.x;
    if (i < CY * 256) {
        int ch = i >> 8, n = i & 255;
        g_peY[i] = pe_val(ch, n >> 4, n & 15, 32);
    } else {
        int j = i - CY * 256;
        if (j < CS * 256) {
            int ch = j >> 8, n = j & 255;
            g_peS[j] = pe_val(ch, n >> 4, n & 15, 16);
        }
    }
}

__global__ void k_addpe_s(const float* __restrict__ S) {
    int i4 = blockIdx.x * 256 + threadIdx.x;
    int i = i4 * 4;
    int n = i & (NN - 1);
    int ch = (i >> 12) % CS;
    float4 s = *(const float4*)&S[i];
    float4 p = *(const float4*)&g_peS[ch * 256 + (n & 255)];
    s.x += p.x; s.y += p.y; s.z += p.z; s.w += p.w;
    *(float4*)&g_Spe[i] = s;
}

__global__ void k_addpe_y(const float* __restrict__ Y) {
    int i4 = blockIdx.x * 256 + threadIdx.x;
    int i = i4 * 4;
    int n = i & (NN - 1);
    int ch = (i >> 12) % CY;
    float4 s = *(const float4*)&Y[i];
    float4 p = *(const float4*)&g_peY[ch * 256 + (n & 255)];
    s.x += p.x; s.y += p.y; s.z += p.z; s.w += p.w;
    *(float4*)&g_Ype[i] = s;
}

// ---------------- S1 projection fused with V = S1 @ Wv ---------------------
__global__ __launch_bounds__(256) void k_proj_sv(
    const float* __restrict__ w_s, const float* __restrict__ b_s,
    const float* __restrict__ g_s, const float* __restrict__ be_s,
    const float* __restrict__ Wv)
{
    __shared__ float in_s[CS * 64];
    __shared__ float wt[CS * CS];
    __shared__ float wv[CS * CS];
    __shared__ float s1[64 * 49];

    int b = blockIdx.y, n0 = blockIdx.x * 64, t = threadIdx.x;
    for (int i = t; i < CS * CS; i += 256) {
        int e = i % CS, c = i / CS;
        wt[i] = w_s[e * CS + c];
        wv[i] = Wv[i];
    }
    const float* src = g_Spe + (b * CS) * NN + n0;
    for (int i = t; i < CS * 64; i += 256) {
        int c = i >> 6, n = i & 63;
        in_s[i] = src[c * NN + n];
    }
    __syncthreads();

    int n = t & 63, eg = t >> 6;
    float acc[12];
#pragma unroll
    for (int j = 0; j < 12; j++) acc[j] = 0.f;
    for (int c = 0; c < CS; c++) {
        float x = in_s[c * 64 + n];
#pragma unroll
        for (int v = 0; v < 3; v++) {
            float4 w4 = *(const float4*)&wt[c * CS + eg * 12 + v * 4];
            acc[v*4+0] += w4.x * x; acc[v*4+1] += w4.y * x;
            acc[v*4+2] += w4.z * x; acc[v*4+3] += w4.w * x;
        }
    }
    float inv = rsqrtf(1.f + 1e-5f);
#pragma unroll
    for (int j = 0; j < 12; j++) {
        int e = eg * 12 + j;
        float y = (acc[j] + b_s[e]) * (g_s[e] * inv) + be_s[e];
        s1[n * 49 + e] = fmaxf(y, 0.f);
    }
    __syncthreads();

#pragma unroll
    for (int j = 0; j < 12; j++) acc[j] = 0.f;
    for (int d = 0; d < CS; d++) {
        float x = s1[n * 49 + d];
#pragma unroll
        for (int v = 0; v < 3; v++) {
            float4 w4 = *(const float4*)&wv[d * CS + eg * 12 + v * 4];
            acc[v*4+0] += w4.x * x; acc[v*4+1] += w4.y * x;
            acc[v*4+2] += w4.z * x; acc[v*4+3] += w4.w * x;
        }
    }
    float* dst = g_V + ((b * NN + n0 + n) * CS) + eg * 12;
#pragma unroll
    for (int v = 0; v < 3; v++)
        *(float4*)&dst[v * 4] = make_float4(acc[v*4], acc[v*4+1], acc[v*4+2], acc[v*4+3]);
}

// ---------------- Y1 projection (96 -> 48) ---------------------------------
__global__ __launch_bounds__(256) void k_proj_y1(
    const float* __restrict__ w_y, const float* __restrict__ b_y,
    const float* __restrict__ g_y, const float* __restrict__ be_y)
{
    __shared__ float in_s[CY * 64];
    __shared__ float wt[CY * CS];

    int b = blockIdx.y, n0 = blockIdx.x * 64, t = threadIdx.x;
    for (int i = t; i < CY * CS; i += 256) {
        int e = i % CS, c = i / CS;
        wt[i] = w_y[e * CY + c];
    }
    const float* src = g_Ype + (b * CY) * NN + n0;
    for (int i = t; i < CY * 64; i += 256) {
        int c = i >> 6, n = i & 63;
        in_s[i] = src[c * NN + n];
    }
    __syncthreads();

    int n = t & 63, eg = t >> 6;
    float acc[12];
#pragma unroll
    for (int j = 0; j < 12; j++) acc[j] = 0.f;
    for (int c = 0; c < CY; c++) {
        float x = in_s[c * 64 + n];
#pragma unroll
        for (int v = 0; v < 3; v++) {
            float4 w4 = *(const float4*)&wt[c * CS + eg * 12 + v * 4];
            acc[v*4+0] += w4.x * x; acc[v*4+1] += w4.y * x;
            acc[v*4+2] += w4.z * x; acc[v*4+3] += w4.w * x;
        }
    }
    float inv = rsqrtf(1.f + 1e-5f);
    float* dst = g_Y1 + ((b * NN + n0 + n) * CS) + eg * 12;
#pragma unroll
    for (int j = 0; j < 12; j++) {
        int e = eg * 12 + j;
        float y = (acc[j] + b_y[e]) * (g_y[e] * inv) + be_y[e];
        dst[j] = fmaxf(y, 0.f);
    }
}

// ---------------- Q/K = Y1 @ Wq / Wk  -> bf16 hi/lo splits ------------------
__global__ __launch_bounds__(256) void k_qk(
    const float* __restrict__ Wq, const float* __restrict__ Wk)
{
    __shared__ float y1[64 * 49];
    __shared__ float wq[CS * CS];
    __shared__ float wk[CS * CS];

    int b = blockIdx.y, n0 = blockIdx.x * 64, t = threadIdx.x;
    for (int i = t; i < CS * CS; i += 256) { wq[i] = Wq[i]; wk[i] = Wk[i]; }
    const float* src = g_Y1 + (b * NN + n0) * CS;
    for (int i = t; i < 64 * CS; i += 256) {
        int n = i / CS, d = i % CS;
        y1[n * 49 + d] = src[i];
    }
    __syncthreads();

    int n = t & 63, eg = t >> 6;
    float aq[12], ak[12];
#pragma unroll
    for (int j = 0; j < 12; j++) { aq[j] = 0.f; ak[j] = 0.f; }
    for (int d = 0; d < CS; d++) {
        float x = y1[n * 49 + d];
#pragma unroll
        for (int v = 0; v < 3; v++) {
            float4 q4 = *(const float4*)&wq[d * CS + eg * 12 + v * 4];
            float4 k4 = *(const float4*)&wk[d * CS + eg * 12 + v * 4];
            aq[v*4+0] += q4.x * x; aq[v*4+1] += q4.y * x;
            aq[v*4+2] += q4.z * x; aq[v*4+3] += q4.w * x;
            ak[v*4+0] += k4.x * x; ak[v*4+1] += k4.y * x;
            ak[v*4+2] += k4.z * x; ak[v*4+3] += k4.w * x;
        }
    }
    int base = (b * NN + n0 + n) * CS + eg * 12;
#pragma unroll
    for (int j = 0; j < 12; j++) {
        __nv_bfloat16 qh = __float2bfloat16(aq[j]);
        __nv_bfloat16 kh = __float2bfloat16(ak[j]);
        g_Qh[base + j] = qh;
        g_Ql[base + j] = __float2bfloat16(aq[j] - __bfloat162float(qh));
        g_Kh[base + j] = kh;
        g_Kl[base + j] = __float2bfloat16(ak[j] - __bfloat162float(kh));
    }
}

// ---------------- logits MMA: L[b][q][k] = exp(SCALE * Q[q]·K[k]) ----------
// Block: 128q x 128k, 8 warps (2 m x 4 n), warp tile 64x32.
// Also produces per-block column sums (over q) into g_psum[b][qblk][k].
#define LPAD 56
#define LOGITS_SMEM (4 * 128 * LPAD * 2)
__global__ __launch_bounds__(256, 2) void k_logits_mma() {
    extern __shared__ __align__(16) unsigned char dsm[];
    __nv_bfloat16* Qsh = (__nv_bfloat16*)dsm;
    __nv_bfloat16* Qsl = Qsh + 128 * LPAD;
    __nv_bfloat16* Ksh = Qsl + 128 * LPAD;
    __nv_bfloat16* Ksl = Ksh + 128 * LPAD;
    __shared__ float colsum[2][128];

    int q0 = blockIdx.x * 128, k0 = blockIdx.y * 128, b = blockIdx.z;
    int t = threadIdx.x, wid = t >> 5, l = t & 31;
    int wm = wid >> 2, wn = wid & 3;

    // stage: 128 rows x 48 bf16 (6 uint4 per row) per matrix
    {
        const __nv_bfloat16* sq = g_Qh + (size_t)(b * NN + q0) * CS;
        for (int i = t; i < 768; i += 256) {
            int r = i / 6, c = i % 6;
            *(uint4*)(Qsh + r * LPAD + c * 8) = *(const uint4*)(sq + r * 48 + c * 8);
        }
        sq = g_Ql + (size_t)(b * NN + q0) * CS;
        for (int i = t; i < 768; i += 256) {
            int r = i / 6, c = i % 6;
            *(uint4*)(Qsl + r * LPAD + c * 8) = *(const uint4*)(sq + r * 48 + c * 8);
        }
        sq = g_Kh + (size_t)(b * NN + k0) * CS;
        for (int i = t; i < 768; i += 256) {
            int r = i / 6, c = i % 6;
            *(uint4*)(Ksh + r * LPAD + c * 8) = *(const uint4*)(sq + r * 48 + c * 8);
        }
        sq = g_Kl + (size_t)(b * NN + k0) * CS;
        for (int i = t; i < 768; i += 256) {
            int r = i / 6, c = i % 6;
            *(uint4*)(Ksl + r * LPAD + c * 8) = *(const uint4*)(sq + r * 48 + c * 8);
        }
    }
    __syncthreads();

    float acc[4][4][4];
#pragma unroll
    for (int mf = 0; mf < 4; mf++)
#pragma unroll
        for (int nf = 0; nf < 4; nf++)
#pragma unroll
            for (int c = 0; c < 4; c++) acc[mf][nf][c] = 0.f;

    int lr = l >> 2, lc = (l & 3) * 2;
#pragma unroll
    for (int ks = 0; ks < 3; ks++) {
        int koff = ks * 16;
        uint32_t bh[4][2], bl[4][2];
#pragma unroll
        for (int nf = 0; nf < 4; nf++) {
            int nb = wn * 32 + nf * 8 + lr;
            bh[nf][0] = *(const uint32_t*)&Ksh[nb * LPAD + koff + lc];
            bh[nf][1] = *(const uint32_t*)&Ksh[nb * LPAD + koff + lc + 8];
            bl[nf][0] = *(const uint32_t*)&Ksl[nb * LPAD + koff + lc];
            bl[nf][1] = *(const uint32_t*)&Ksl[nb * LPAD + koff + lc + 8];
        }
#pragma unroll
        for (int mf = 0; mf < 4; mf++) {
            int mb = wm * 64 + mf * 16;
            uint32_t ah[4], al[4];
            ah[0] = *(const uint32_t*)&Qsh[(mb + lr) * LPAD + koff + lc];
            ah[1] = *(const uint32_t*)&Qsh[(mb + 8 + lr) * LPAD + koff + lc];
            ah[2] = *(const uint32_t*)&Qsh[(mb + lr) * LPAD + koff + lc + 8];
            ah[3] = *(const uint32_t*)&Qsh[(mb + 8 + lr) * LPAD + koff + lc + 8];
            al[0] = *(const uint32_t*)&Qsl[(mb + lr) * LPAD + koff + lc];
            al[1] = *(const uint32_t*)&Qsl[(mb + 8 + lr) * LPAD + koff + lc];
            al[2] = *(const uint32_t*)&Qsl[(mb + lr) * LPAD + koff + lc + 8];
            al[3] = *(const uint32_t*)&Qsl[(mb + 8 + lr) * LPAD + koff + lc + 8];
#pragma unroll
            for (int nf = 0; nf < 4; nf++) {
                mma16816(acc[mf][nf], ah, bh[nf]);
                mma16816(acc[mf][nf], ah, bl[nf]);
                mma16816(acc[mf][nf], al, bh[nf]);
            }
        }
    }

    // epilogue: exp, store, column sums over q
    float s0[4] = {0.f, 0.f, 0.f, 0.f}, s1[4] = {0.f, 0.f, 0.f, 0.f};
#pragma unroll
    for (int mf = 0; mf < 4; mf++) {
        int r = q0 + wm * 64 + mf * 16 + lr;
#pragma unroll
        for (int nf = 0; nf < 4; nf++) {
            int col = k0 + wn * 32 + nf * 8 + lc;
            float e0 = __expf(acc[mf][nf][0] * SCALE);
            float e1 = __expf(acc[mf][nf][1] * SCALE);
            float e2 = __expf(acc[mf][nf][2] * SCALE);
            float e3 = __expf(acc[mf][nf][3] * SCALE);
            *(float2*)&g_L[((size_t)b * NN + r) * NN + col]     = make_float2(e0, e1);
            *(float2*)&g_L[((size_t)b * NN + r + 8) * NN + col] = make_float2(e2, e3);
            s0[nf] += e0 + e2;
            s1[nf] += e1 + e3;
        }
    }
#pragma unroll
    for (int nf = 0; nf < 4; nf++) {
#pragma unroll
        for (int o = 4; o <= 16; o <<= 1) {
            s0[nf] += __shfl_xor_sync(0xffffffffu, s0[nf], o);
            s1[nf] += __shfl_xor_sync(0xffffffffu, s1[nf], o);
        }
        if (lr == 0) {
            int col = wn * 32 + nf * 8 + l * 2;   // l in 0..3 here
            colsum[wm][col]     = s0[nf];
            colsum[wm][col + 1] = s1[nf];
        }
    }
    __syncthreads();
    if (t < 128)
        g_psum[(b * 32 + blockIdx.x) * NN + k0 + t] = colsum[0][t] + colsum[1][t];
}

// ---------------- vprime: fold 1/colsum into V, transpose, bf16 split -------
__global__ __launch_bounds__(256) void k_vprime() {
    int t = threadIdx.x;
    int k = blockIdx.x * 256 + t, b = blockIdx.y;
    float s = 0.f;
#pragma unroll
    for (int i = 0; i < 32; i++) s += g_psum[(b * 32 + i) * NN + k];
    float iz = 1.f / s;
    const float* v = g_V + (size_t)(b * NN + k) * CS;
#pragma unroll
    for (int d = 0; d < CS; d++) {
        float val = v[d] * iz;
        __nv_bfloat16 h = __float2bfloat16(val);
        g_Vth[(b * CS + d) * NN + k] = h;
        g_Vtl[(b * CS + d) * NN + k] = __float2bfloat16(val - __bfloat162float(h));
    }
}

// ---------------- AV MMA: Xp[c][b][q][d] = sum_{k in chunk} P[q][k] V'[k][d]
// Block: 128q x 48d, k-chunk 1024 (8 subtiles of 128). 8 warps (4 m x 2 n).
#define APAD 136
#define AV_SMEM ((2 * 128 * APAD + 2 * 48 * APAD) * 2)
__global__ __launch_bounds__(256, 2) void k_av_mma() {
    extern __shared__ __align__(16) unsigned char dsm[];
    __nv_bfloat16* Ah = (__nv_bfloat16*)dsm;
    __nv_bfloat16* Al = Ah + 128 * APAD;
    __nv_bfloat16* Bh = Al + 128 * APAD;
    __nv_bfloat16* Bl = Bh + 48 * APAD;

    int q0 = blockIdx.x * 128, cz = blockIdx.y, b = blockIdx.z;
    int ck0 = cz * 1024;
    int t = threadIdx.x, wid = t >> 5, l = t & 31;
    int wm = wid >> 1, wn = wid & 1;
    int lr = l >> 2, lc = (l & 3) * 2;

    float acc[2][3][4];
#pragma unroll
    for (int mf = 0; mf < 2; mf++)
#pragma unroll
        for (int nf = 0; nf < 3; nf++)
#pragma unroll
            for (int c = 0; c < 4; c++) acc[mf][nf][c] = 0.f;

    for (int st = 0; st < 8; st++) {
        __syncthreads();
        int kbase = ck0 + st * 128;
        // stage A: L[q0..+127][kbase..+127] fp32 -> bf16 h/l
        {
            int r = t >> 1, half = t & 1;
            const float* src = &g_L[((size_t)b * NN + q0 + r) * NN + kbase];
#pragma unroll
            for (int j = 0; j < 16; j++) {
                int cc = half * 16 + j;
                float4 x = *(const float4*)&src[cc * 4];
                __nv_bfloat16 h0 = __float2bfloat16(x.x);
                __nv_bfloat16 h1 = __float2bfloat16(x.y);
                __nv_bfloat16 h2 = __float2bfloat16(x.z);
                __nv_bfloat16 h3 = __float2bfloat16(x.w);
                *(uint2*)(Ah + r * APAD + cc * 4) =
                    make_uint2(bf2u(h0, h1), bf2u(h2, h3));
                *(uint2*)(Al + r * APAD + cc * 4) = make_uint2(
                    bf2u(__float2bfloat16(x.x - __bfloat162float(h0)),
                         __float2bfloat16(x.y - __bfloat162float(h1))),
                    bf2u(__float2bfloat16(x.z - __bfloat162float(h2)),
                         __float2bfloat16(x.w - __bfloat162float(h3))));
            }
        }
        // stage B: Vth/Vtl[b][d][kbase..+127]
        for (int i = t; i < 1536; i += 256) {
            int m = i / 768, j = i % 768;
            int d = j / 16, sg = j % 16;
            const __nv_bfloat16* src = (m ? g_Vtl : g_Vth) + (size_t)(b * CS + d) * NN + kbase + sg * 8;
            __nv_bfloat16* dst = (m ? Bl : Bh) + d * APAD + sg * 8;
            *(uint4*)dst = *(const uint4*)src;
        }
        __syncthreads();

#pragma unroll
        for (int ksi = 0; ksi < 8; ksi++) {
            int koff = ksi * 16;
            uint32_t bh[3][2], bl[3][2];
#pragma unroll
            for (int nf = 0; nf < 3; nf++) {
                int nb = wn * 24 + nf * 8 + lr;
                bh[nf][0] = *(const uint32_t*)&Bh[nb * APAD + koff + lc];
                bh[nf][1] = *(const uint32_t*)&Bh[nb * APAD + koff + lc + 8];
                bl[nf][0] = *(const uint32_t*)&Bl[nb * APAD + koff + lc];
                bl[nf][1] = *(const uint32_t*)&Bl[nb * APAD + koff + lc + 8];
            }
#pragma unroll
            for (int mf = 0; mf < 2; mf++) {
                int mb = wm * 32 + mf * 16;
                uint32_t ah[4], al[4];
                ah[0] = *(const uint32_t*)&Ah[(mb + lr) * APAD + koff + lc];
                ah[1] = *(const uint32_t*)&Ah[(mb + 8 + lr) * APAD + koff + lc];
                ah[2] = *(const uint32_t*)&Ah[(mb + lr) * APAD + koff + lc + 8];
                ah[3] = *(const uint32_t*)&Ah[(mb + 8 + lr) * APAD + koff + lc + 8];
                al[0] = *(const uint32_t*)&Al[(mb + lr) * APAD + koff + lc];
                al[1] = *(const uint32_t*)&Al[(mb + 8 + lr) * APAD + koff + lc];
                al[2] = *(const uint32_t*)&Al[(mb + lr) * APAD + koff + lc + 8];
                al[3] = *(const uint32_t*)&Al[(mb + 8 + lr) * APAD + koff + lc + 8];
#pragma unroll
                for (int nf = 0; nf < 3; nf++) {
                    mma16816(acc[mf][nf], ah, bh[nf]);
                    mma16816(acc[mf][nf], ah, bl[nf]);
                    mma16816(acc[mf][nf], al, bh[nf]);
                }
            }
        }
    }

#pragma unroll
    for (int mf = 0; mf < 2; mf++) {
        int r = q0 + wm * 32 + mf * 16 + lr;
#pragma unroll
        for (int nf = 0; nf < 3; nf++) {
            int col = wn * 24 + nf * 8 + lc;
            float* base = &g_Xp[((size_t)(cz * BB + b) * NN + r) * CS + col];
            *(float2*)base = make_float2(acc[mf][nf][0], acc[mf][nf][1]);
            *(float2*)(base + 8 * CS) = make_float2(acc[mf][nf][2], acc[mf][nf][3]);
        }
    }
}

// ---------------- conv3d 3x3x3 (96 -> 96), SAME, f32x2, ci-split-2 ---------
__global__ __launch_bounds__(256) void k_conv3d(const float* __restrict__ w3) {
    __shared__ __align__(16) float in_s[3 * 18 * 18];
    __shared__ __align__(16) float ws[27][16];

    int cog = blockIdx.x, d = blockIdx.y;
    int b = blockIdx.z >> 1, half = blockIdx.z & 1;
    int t = threadIdx.x, h = t >> 4, w = t & 15;

    unsigned long long acc[8];
#pragma unroll
    for (int j = 0; j < 8; j++) acc[j] = 0ull;

    for (int ci0 = 0; ci0 < 48; ci0++) {
        int ci = half * 48 + ci0;
        const float* src = g_Ype + (size_t)(b * CY + ci) * NN;
        for (int i = t; i < 3 * 324; i += 256) {
            int dd = i / 324, rem = i - dd * 324, r = rem / 18, c = rem - r * 18;
            int z = d + dd - 1, y = r - 1, x = c - 1;
            float v = 0.f;
            if (z >= 0 && z < 16 && y >= 0 && y < 16 && x >= 0 && x < 16)
                v = src[z * 256 + y * 16 + x];
            in_s[i] = v;
        }
        for (int i = t; i < 16 * 27; i += 256) {
            int tap = i % 27, co = i / 27;
            ws[tap][co] = w3[(size_t)(cog * 16 + co) * (CY * 27) + ci * 27 + tap];
        }
        __syncthreads();

        float in_r[27];
#pragma unroll
        for (int dd = 0; dd < 3; dd++)
#pragma unroll
            for (int dy = 0; dy < 3; dy++)
#pragma unroll
                for (int dx = 0; dx < 3; dx++)
                    in_r[dd*9+dy*3+dx] = in_s[dd*324 + (h+dy)*18 + (w+dx)];

#pragma unroll
        for (int tap = 0; tap < 27; tap++) {
            unsigned long long xx;
            asm("mov.b64 %0, {%1, %1};" : "=l"(xx) : "f"(in_r[tap]));
#pragma unroll
            for (int j = 0; j < 8; j++) {
                unsigned long long ww = *(const unsigned long long*)&ws[tap][2 * j];
                fma2(acc[j], xx, ww);
            }
        }
        __syncthreads();
    }
    int n = d * 256 + t;
    float* dst = g_Y3p + (size_t)half * (BB * CY * NN) + (size_t)(b * CY + cog * 16) * NN + n;
#pragma unroll
    for (int j = 0; j < 8; j++) {
        float lo, hi;
        asm("mov.b64 {%0, %1}, %2;" : "=f"(lo), "=f"(hi) : "l"(acc[j]));
        dst[(2 * j) * NN]     = lo;
        dst[(2 * j + 1) * NN] = hi;
    }
}

// ---------------- Z output: bn_relu(X @ w_o) * Spe -> out[:, 0:48] ---------
__global__ __launch_bounds__(256) void k_zout(
    const float* __restrict__ w_o, const float* __restrict__ b_o,
    const float* __restrict__ g_o, const float* __restrict__ be_o,
    float* __restrict__ out)
{
    __shared__ float xs[CS * 64];
    __shared__ float wot[CS * CS];

    int b = blockIdx.y, n0 = blockIdx.x * 64, t = threadIdx.x;
    for (int i = t; i < CS * CS; i += 256) {
        int e = i % CS, d = i / CS;
        wot[i] = w_o[e * CS + d];
    }
    {
        int n = t & 63, v = t >> 6;
        const size_t cstride = (size_t)BB * NN * CS;
        const float* src = g_Xp + (size_t)(b * NN + n0 + n) * CS;
#pragma unroll
        for (int r = 0; r < 3; r++) {
            int dv = v + r * 4;
            float4 x = *(const float4*)&src[dv * 4];
            float4 x1 = *(const float4*)&src[cstride + dv * 4];
            float4 x2 = *(const float4*)&src[2 * cstride + dv * 4];
            float4 x3 = *(const float4*)&src[3 * cstride + dv * 4];
            x.x += x1.x + x2.x + x3.x;
            x.y += x1.y + x2.y + x3.y;
            x.z += x1.z + x2.z + x3.z;
            x.w += x1.w + x2.w + x3.w;
            xs[(dv*4+0)*64+n] = x.x; xs[(dv*4+1)*64+n] = x.y;
            xs[(dv*4+2)*64+n] = x.z; xs[(dv*4+3)*64+n] = x.w;
        }
    }
    __syncthreads();

    int n = t & 63, eg = t >> 6;
    float acc[12];
#pragma unroll
    for (int j = 0; j < 12; j++) acc[j] = 0.f;
    for (int d = 0; d < CS; d++) {
        float x = xs[d * 64 + n];
#pragma unroll
        for (int v = 0; v < 3; v++) {
            float4 w4 = *(const float4*)&wot[d * CS + eg * 12 + v * 4];
            acc[v*4+0] += w4.x * x; acc[v*4+1] += w4.y * x;
            acc[v*4+2] += w4.z * x; acc[v*4+3] += w4.w * x;
        }
    }
    float inv = rsqrtf(1.f + 1e-5f);
#pragma unroll
    for (int j = 0; j < 12; j++) {
        int e = eg * 12 + j;
        float y = (acc[j] + b_o[e]) * (g_o[e] * inv) + be_o[e];
        y = fmaxf(y, 0.f);
        out[(b * 96 + e) * NN + n0 + n] = y * g_Spe[(b * CS + e) * NN + n0 + n];
    }
}

// ---------------- Y2 output: bn_relu((Y3p0+Y3p1+b3) @ w_y2) -> out[:,48:96] -
__global__ __launch_bounds__(256) void k_y2out(
    const float* __restrict__ w_y2, const float* __restrict__ b_y2,
    const float* __restrict__ g_y2, const float* __restrict__ be_y2,
    const float* __restrict__ b3, float* __restrict__ out)
{
    __shared__ float in_s[CY * 64];
    __shared__ float wt[CY * CS];

    int b = blockIdx.y, n0 = blockIdx.x * 64, t = threadIdx.x;
    for (int i = t; i < CY * CS; i += 256) {
        int e = i % CS, c = i / CS;
        wt[i] = w_y2[e * CY + c];
    }
    const size_t hstride = (size_t)BB * CY * NN;
    const float* src = g_Y3p + (size_t)(b * CY) * NN + n0;
    for (int i = t; i < CY * 64; i += 256) {
        int c = i >> 6, n = i & 63;
        in_s[i] = src[c * NN + n] + src[hstride + c * NN + n] + b3[c];
    }
    __syncthreads();

    int n = t & 63, eg = t >> 6;
    float acc[12];
#pragma unroll
    for (int j = 0; j < 12; j++) acc[j] = 0.f;
    for (int c = 0; c < CY; c++) {
        float x = in_s[c * 64 + n];
#pragma unroll
        for (int v = 0; v < 3; v++) {
            float4 w4 = *(const float4*)&wt[c * CS + eg * 12 + v * 4];
            acc[v*4+0] += w4.x * x; acc[v*4+1] += w4.y * x;
            acc[v*4+2] += w4.z * x; acc[v*4+3] += w4.w * x;
        }
    }
    float inv = rsqrtf(1.f + 1e-5f);
#pragma unroll
    for (int j = 0; j < 12; j++) {
        int e = eg * 12 + j;
        float y = (acc[j] + b_y2[e]) * (g_y2[e] * inv) + be_y2[e];
        out[(b * 96 + 48 + e) * NN + n0 + n] = fmaxf(y, 0.f);
    }
}

// ---------------- launch ----------------------------------------------------
extern "C" void kernel_launch(void* const* d_in, const int* in_sizes, int n_in,
                              void* d_out, int out_size)
{
    const float* Y    = (const float*)d_in[0];
    const float* S    = (const float*)d_in[1];
    const float* w_s  = (const float*)d_in[2];
    const float* b_s  = (const float*)d_in[3];
    const float* g_s  = (const float*)d_in[4];
    const float* be_s = (const float*)d_in[5];
    const float* w_y  = (const float*)d_in[6];
    const float* b_y  = (const float*)d_in[7];
    const float* g_y  = (const float*)d_in[8];
    const float* be_y = (const float*)d_in[9];
    const float* Wq   = (const float*)d_in[10];
    const float* Wk   = (const float*)d_in[11];
    const float* Wv   = (const float*)d_in[12];
    const float* w_o  = (const float*)d_in[13];
    const float* b_o  = (const float*)d_in[14];
    const float* g_o  = (const float*)d_in[15];
    const float* be_o = (const float*)d_in[16];
    const float* w3   = (const float*)d_in[17];
    const float* b3   = (const float*)d_in[18];
    const float* w_y2 = (const float*)d_in[19];
    const float* b_y2 = (const float*)d_in[20];
    const float* g_y2 = (const float*)d_in[21];
    const float* be_y2= (const float*)d_in[22];
    float* out = (float*)d_out;

    static int attr_done = 0;
    if (!attr_done) {
        cudaFuncSetAttribute(k_logits_mma,
            cudaFuncAttributeMaxDynamicSharedMemorySize, LOGITS_SMEM);
        cudaFuncSetAttribute(k_av_mma,
            cudaFuncAttributeMaxDynamicSharedMemorySize, AV_SMEM);
        attr_done = 1;
    }

    k_petab<<<144, 256>>>();
    k_addpe_s<<<BB*CS*NN/1024, 256>>>(S);
    k_addpe_y<<<BB*CY*NN/1024, 256>>>(Y);

    k_proj_sv<<<dim3(NN/64, BB), 256>>>(w_s, b_s, g_s, be_s, Wv);
    k_proj_y1<<<dim3(NN/64, BB), 256>>>(w_y, b_y, g_y, be_y);
    k_qk     <<<dim3(NN/64, BB), 256>>>(Wq, Wk);

    k_logits_mma<<<dim3(32, 32, BB), 256, LOGITS_SMEM>>>();
    k_vprime    <<<dim3(16, BB), 256>>>();
    k_av_mma    <<<dim3(32, 4, BB), 256, AV_SMEM>>>();

    k_conv3d<<<dim3(CY/16, 16, BB*2), 256>>>(w3);

    k_zout <<<dim3(NN/64, BB), 256>>>(w_o, b_o, g_o, be_o, out);
    k_y2out<<<dim3(NN/64, BB), 256>>>(w_y2, b_y2, g_y2, be_y2, b3, out);
}